// round 1
// baseline (speedup 1.0000x reference)
#include <cuda_runtime.h>
#include <cstdint>

#define IN_DIM      1024
#define ANCHORS     8
#define KOUT        16            // ANCHOR_NUM * CLASS_NUM
#define ROWS_TOTAL  32768         // 64 * 512
#define TASKS_TOTAL 4096          // ROWS_TOTAL / 8 (8 rows per warp-task)
#define NOUT_PER    262144        // 64*512*8
#define GRID_MAIN   296
#define CTA_THREADS 256
#define SUB_STRIDE  2050          // 128*16 + 2 ull pad (bank de-conflict between sub blocks)
#define SMEM_BYTES  (4 * SUB_STRIDE * 8)

__device__ float g_nll_sum;
__device__ int   g_valid_cnt;

typedef unsigned long long ull;

__device__ __forceinline__ ull fma2(ull a, ull b, ull c) {
    ull d;
    asm("fma.rn.f32x2 %0, %1, %2, %3;" : "=l"(d) : "l"(a), "l"(b), "l"(c));
    return d;
}
__device__ __forceinline__ ull add2(ull a, ull b) {
    ull d;
    asm("add.rn.f32x2 %0, %1, %2;" : "=l"(d) : "l"(a), "l"(b));
    return d;
}
__device__ __forceinline__ float lo32(ull v) { return __uint_as_float((unsigned)(v & 0xffffffffu)); }
__device__ __forceinline__ float hi32(ull v) { return __uint_as_float((unsigned)(v >> 32)); }
__device__ __forceinline__ ull pack2(float lo, float hi) {
    return ((ull)__float_as_uint(hi) << 32) | (ull)__float_as_uint(lo);
}

__global__ void zero_kernel() {
    g_nll_sum = 0.0f;
    g_valid_cnt = 0;
}

__global__ void finalize_kernel(float* __restrict__ out) {
    out[0] = g_nll_sum / fmaxf((float)g_valid_cnt, 1.0f);
}

extern __shared__ ull ws[];  // [4][SUB_STRIDE]: pair-interleaved W, padded per sub-block

__global__ __launch_bounds__(CTA_THREADS)
void rpn_main_kernel(const float* __restrict__ X,
                     const float* __restrict__ W,
                     const float* __restrict__ bvec,
                     const int*   __restrict__ labels,
                     float* __restrict__ out)
{
    const int tid  = threadIdx.x;
    const int warp = tid >> 5;
    const int lane = tid & 31;
    const int sub  = lane & 3;        // column-chunk of 256 elems (128 pairs)
    const int rloc = lane >> 2;       // row within 8-row warp task

    // ---- Stage W into shared as f32x2 pairs: ws[sub][local_pair*16 + k] ----
    // pair p pairs columns j=2p and j=2p+1; value k in [0,16)
    for (int i = tid; i < 512 * KOUT; i += CTA_THREADS) {
        int p = i >> 4;
        int k = i & 15;
        float flo = W[p * 32 + k];          // W[(2p)*16 + k]
        float fhi = W[p * 32 + 16 + k];     // W[(2p+1)*16 + k]
        ws[(p >> 7) * SUB_STRIDE + (p & 127) * KOUT + k] = pack2(flo, fhi);
    }
    __syncthreads();

    const ull* __restrict__ wp = ws + sub * SUB_STRIDE;

    float run_nll = 0.0f;
    int   run_cnt = 0;

    // Balanced persistent task ranges (each task = 8 rows handled by one warp)
    const int tstart = (int)(((long long)TASKS_TOTAL * blockIdx.x) / gridDim.x);
    const int tend   = (int)(((long long)TASKS_TOTAL * (blockIdx.x + 1)) / gridDim.x);

    for (int t = tstart + warp; t < tend; t += (CTA_THREADS / 32)) {
        const int row = t * 8 + rloc;
        const ulonglong2* __restrict__ xp =
            (const ulonglong2*)(X + (size_t)row * IN_DIM + sub * 256);

        ull acc[KOUT];
        #pragma unroll
        for (int k = 0; k < KOUT; k++) acc[k] = 0ULL;

        // 64 iterations * 4 floats (2 pairs) = 256 columns per thread
        #pragma unroll 2
        for (int it = 0; it < 64; ++it) {
            ulonglong2 xv = __ldg(&xp[it]);
            const ull* w0 = wp + (it * 2) * KOUT;
            #pragma unroll
            for (int k = 0; k < KOUT; k++) acc[k] = fma2(xv.x, w0[k], acc[k]);
            #pragma unroll
            for (int k = 0; k < KOUT; k++) acc[k] = fma2(xv.y, w0[KOUT + k], acc[k]);
        }

        // Combine the 4 column-chunk partials (lanes 4r..4r+3)
        #pragma unroll
        for (int k = 0; k < KOUT; k++) {
            ull v = acc[k];
            v = add2(v, __shfl_xor_sync(0xffffffffu, v, 1));
            v = add2(v, __shfl_xor_sync(0xffffffffu, v, 2));
            acc[k] = v;
        }

        if (sub == 0) {
            float logit[KOUT];
            #pragma unroll
            for (int k = 0; k < KOUT; k++)
                logit[k] = lo32(acc[k]) + hi32(acc[k]) + __ldg(&bvec[k]);

            const int4 lab0 = __ldg((const int4*)(labels + (size_t)row * ANCHORS));
            const int4 lab1 = __ldg((const int4*)(labels + (size_t)row * ANCHORS) + 1);
            int lab[ANCHORS] = {lab0.x, lab0.y, lab0.z, lab0.w,
                                lab1.x, lab1.y, lab1.z, lab1.w};

            #pragma unroll
            for (int a = 0; a < ANCHORS; a++) {
                float l0 = logit[2 * a];
                float l1 = logit[2 * a + 1];
                int   pred  = (l1 > l0) ? 1 : 0;   // argmax, first-index tie like jnp
                int   lb    = lab[a];
                bool  valid = (lb != -1);
                float chosen = (lb == 1) ? l1 : l0;  // max(lb,0) selects class
                float other  = (lb == 1) ? l0 : l1;
                float d = other - chosen;
                float nll = (d > 0.0f) ? (d + log1pf(expf(-d))) : log1pf(expf(d));
                if (valid) { run_nll += nll; run_cnt++; }
                out[1 + (size_t)row * ANCHORS + a] = (float)pred;
                out[1 + NOUT_PER + (size_t)row * ANCHORS + a] =
                    (pred == 1 && valid) ? 1.0f : 0.0f;
            }
        }
    }

    // Warp reduction of loss partials, then one atomic per warp
    #pragma unroll
    for (int off = 16; off > 0; off >>= 1) {
        run_nll += __shfl_down_sync(0xffffffffu, run_nll, off);
        run_cnt += __shfl_down_sync(0xffffffffu, run_cnt, off);
    }
    if (lane == 0) {
        atomicAdd(&g_nll_sum, run_nll);
        atomicAdd(&g_valid_cnt, run_cnt);
    }
}

extern "C" void kernel_launch(void* const* d_in, const int* in_sizes, int n_in,
                              void* d_out, int out_size)
{
    // Identify inputs by element count (robust to ordering)
    const float* X = nullptr;
    const float* W = nullptr;
    const float* b = nullptr;
    const int* labels = nullptr;
    for (int i = 0; i < n_in; i++) {
        switch (in_sizes[i]) {
            case 33554432: X = (const float*)d_in[i]; break;       // 64*512*1024
            case 16384:    W = (const float*)d_in[i]; break;       // 1024*16
            case KOUT:     b = (const float*)d_in[i]; break;       // 16
            case NOUT_PER: labels = (const int*)d_in[i]; break;    // 64*512*8
            default: break;
        }
    }
    float* out = (float*)d_out;

    static bool attr_set = false;  // idempotent attribute set (not a work guard)
    if (!attr_set) {
        cudaFuncSetAttribute(rpn_main_kernel,
                             cudaFuncAttributeMaxDynamicSharedMemorySize, SMEM_BYTES);
        attr_set = true;
    }

    zero_kernel<<<1, 1>>>();
    rpn_main_kernel<<<GRID_MAIN, CTA_THREADS, SMEM_BYTES>>>(X, W, b, labels, out);
    finalize_kernel<<<1, 1>>>(out);
}

// round 2
// speedup vs baseline: 1.1648x; 1.1648x over previous
#include <cuda_runtime.h>
#include <cstdint>

typedef unsigned long long ull;

#define IN_DIM   1024
#define KOUT     16
#define ROWS     32768
#define TILE_R   16
#define NTILES   2048          // ROWS / TILE_R
#define NOUT     262144        // 64*512*8
#define GRID     152
#define NTHR     256

// ---- shared memory layout (bytes) ----
#define WS_ULLS      8240
#define WS_BYTES     (WS_ULLS*8)             // 65920: packed W pairs
#define XROW_BYTES   4112                    // 1024*4 + 16B pad (bank de-skew)
#define STAGE_BYTES  (TILE_R*XROW_BYTES)     // 65792 per stage
#define XS_OFF       WS_BYTES
#define RED_OFF      (XS_OFF + 2*STAGE_BYTES)     // 197504
#define RED_BYTES    (8*16*16*8)                  // 16384: per-warp partials
#define LOG_OFF      (RED_OFF + RED_BYTES)        // 213888: logits 16x16 f32
#define BIAS_OFF     (LOG_OFF + 16*16*4)          // 214912
#define PART_OFF     (BIAS_OFF + 64)              // CTA loss partials
#define SMEM_TOTAL   (PART_OFF + 128)             // 215104 B

__device__ float        g_nll;
__device__ int          g_cnt;
__device__ unsigned int g_ticket;

__device__ __forceinline__ ull fma2(ull a, ull b, ull c) {
    ull d;
    asm("fma.rn.f32x2 %0, %1, %2, %3;" : "=l"(d) : "l"(a), "l"(b), "l"(c));
    return d;
}
__device__ __forceinline__ ull add2(ull a, ull b) {
    ull d;
    asm("add.rn.f32x2 %0, %1, %2;" : "=l"(d) : "l"(a), "l"(b));
    return d;
}
__device__ __forceinline__ float lo32(ull v) { return __uint_as_float((unsigned)(v & 0xffffffffu)); }
__device__ __forceinline__ float hi32(ull v) { return __uint_as_float((unsigned)(v >> 32)); }
__device__ __forceinline__ ull pack2(float lo, float hi) {
    return ((ull)__float_as_uint(hi) << 32) | (ull)__float_as_uint(lo);
}

__device__ __forceinline__ void cp16(uint32_t s, const void* g) {
    asm volatile("cp.async.cg.shared.global [%0], [%1], 16;" :: "r"(s), "l"(g) : "memory");
}
#define CP_COMMIT() asm volatile("cp.async.commit_group;" ::: "memory")
#define CP_WAIT1()  asm volatile("cp.async.wait_group 1;" ::: "memory")

__device__ __forceinline__ void issue_tile_load(const float* __restrict__ X,
                                                uint32_t smem_base, int tile,
                                                int stg, int tid) {
    const char* g = (const char*)X + (size_t)tile * TILE_R * IN_DIM * 4;
    uint32_t s0 = smem_base + XS_OFF + (uint32_t)stg * STAGE_BYTES + (uint32_t)tid * 16u;
    #pragma unroll
    for (int j = 0; j < TILE_R; j++) {
        cp16(s0 + (uint32_t)j * XROW_BYTES, g + (size_t)j * 4096 + (size_t)tid * 16);
    }
}

__global__ __launch_bounds__(NTHR, 1)
void rpn_fused_kernel(const float* __restrict__ X,
                      const float* __restrict__ W,
                      const float* __restrict__ bvec,
                      const int*   __restrict__ labels,
                      float* __restrict__ out)
{
    extern __shared__ char smem[];
    ull*   ws      = (ull*)smem;
    ull*   red     = (ull*)(smem + RED_OFF);
    float* logit_s = (float*)(smem + LOG_OFF);
    float* bias_s  = (float*)(smem + BIAS_OFF);
    float* pn      = (float*)(smem + PART_OFF);
    int*   pc      = (int*)(smem + PART_OFF + 32);

    const int tid  = threadIdx.x;
    const int w    = tid >> 5;
    const int lane = tid & 31;
    const int sub  = lane & 3;     // 4 col-chunks of 32 cols within warp's 128
    const int rpos = lane >> 2;    // row slot; thread handles tile rows rpos, rpos+8

    const uint32_t smem_base = (uint32_t)__cvta_generic_to_shared(smem);

    // Kick off the first tile load ASAP (independent of W staging)
    int t0 = blockIdx.x;
    if (t0 < NTILES) issue_tile_load(X, smem_base, t0, 0, tid);
    CP_COMMIT();

    // Stage W as col-pair-interleaved f32x2 with per-16-pair bank pad:
    // ws[p*16 + (p>>4) + k] = (W[2p][k], W[2p+1][k])
    for (int i = tid; i < 512 * KOUT; i += NTHR) {
        int p = i >> 4, k = i & 15;
        ws[p * 16 + (p >> 4) + k] = pack2(W[p * 32 + k], W[p * 32 + 16 + k]);
    }
    if (tid < KOUT) bias_s[tid] = bvec[tid];
    __syncthreads();

    // Per-thread W base: pairs [w*64 + sub*16, +16)
    const ull* __restrict__ wp = ws + ((w * 64 + sub * 16) * 16 + w * 4 + sub);
    const char* xs0 = smem + XS_OFF + rpos * XROW_BYTES + (w * 512 + sub * 128);

    float run_nll = 0.0f;
    int   run_cnt = 0;

    int stg = 0;
    for (int t = blockIdx.x; t < NTILES; t += GRID, stg ^= 1) {
        int tn = t + GRID;
        if (tn < NTILES) issue_tile_load(X, smem_base, tn, stg ^ 1, tid);
        CP_COMMIT();
        CP_WAIT1();
        __syncthreads();

        const char* xb = xs0 + stg * STAGE_BYTES;
        ull accA[KOUT], accB[KOUT];
        #pragma unroll
        for (int k = 0; k < KOUT; k++) { accA[k] = 0ULL; accB[k] = 0ULL; }

        #pragma unroll
        for (int it = 0; it < 8; it++) {
            ulonglong2 xa = *(const ulonglong2*)(xb + it * 16);
            ulonglong2 xv = *(const ulonglong2*)(xb + 8 * XROW_BYTES + it * 16);
            const ull* w0 = wp + it * 32;
            #pragma unroll
            for (int k = 0; k < KOUT; k++) {
                ull wv = w0[k];
                accA[k] = fma2(xa.x, wv, accA[k]);
                accB[k] = fma2(xv.x, wv, accB[k]);
            }
            #pragma unroll
            for (int k = 0; k < KOUT; k++) {
                ull wv = w0[16 + k];
                accA[k] = fma2(xa.y, wv, accA[k]);
                accB[k] = fma2(xv.y, wv, accB[k]);
            }
        }

        // Reduce over the 4 sub lanes (butterfly)
        #pragma unroll
        for (int k = 0; k < KOUT; k++) {
            accA[k] = add2(accA[k], __shfl_xor_sync(0xffffffffu, accA[k], 1));
            accB[k] = add2(accB[k], __shfl_xor_sync(0xffffffffu, accB[k], 1));
        }
        #pragma unroll
        for (int k = 0; k < KOUT; k++) {
            accA[k] = add2(accA[k], __shfl_xor_sync(0xffffffffu, accA[k], 2));
            accB[k] = add2(accB[k], __shfl_xor_sync(0xffffffffu, accB[k], 2));
        }

        if (sub == 0) {
            ull* rp = red + w * 256 + rpos * 16;
            #pragma unroll
            for (int k = 0; k < KOUT; k++) { rp[k] = accA[k]; rp[128 + k] = accB[k]; }
        }
        __syncthreads();

        // Cross-warp reduce: thread (row, k)
        {
            int row = tid >> 4, k = tid & 15;
            ull s = red[row * 16 + k];
            #pragma unroll
            for (int ww = 1; ww < 8; ww++) s = add2(s, red[ww * 256 + row * 16 + k]);
            logit_s[row * 16 + k] = lo32(s) + hi32(s) + bias_s[k];
        }
        __syncthreads();

        // Epilogue: 128 threads = (row, anchor)
        if (tid < 128) {
            int row = tid >> 3, a = tid & 7;
            float l0 = logit_s[row * 16 + 2 * a];
            float l1 = logit_s[row * 16 + 2 * a + 1];
            int gidx = t * 128 + tid;
            int lb = __ldg(&labels[gidx]);
            bool valid = (lb != -1);
            int  pred  = (l1 > l0) ? 1 : 0;
            float chosen = (lb == 1) ? l1 : l0;
            float other  = (lb == 1) ? l0 : l1;
            float d = other - chosen;
            float nll = (d > 0.0f) ? (d + log1pf(expf(-d))) : log1pf(expf(d));
            if (valid) { run_nll += nll; run_cnt++; }
            out[1 + gidx]        = (float)pred;
            out[1 + NOUT + gidx] = (pred == 1 && valid) ? 1.0f : 0.0f;
        }
        __syncthreads();   // protects stage stg from next-next load
    }

    // ---- loss reduction: warp -> CTA -> chip (last-CTA ticket) ----
    #pragma unroll
    for (int off = 16; off > 0; off >>= 1) {
        run_nll += __shfl_down_sync(0xffffffffu, run_nll, off);
        run_cnt += __shfl_down_sync(0xffffffffu, run_cnt, off);
    }
    if (lane == 0) { pn[w] = run_nll; pc[w] = run_cnt; }
    __syncthreads();
    if (tid == 0) {
        float s = 0.0f; int c = 0;
        #pragma unroll
        for (int ww = 0; ww < 8; ww++) { s += pn[ww]; c += pc[ww]; }
        atomicAdd(&g_nll, s);
        atomicAdd(&g_cnt, c);
        __threadfence();
        unsigned tk = atomicAdd(&g_ticket, 1u);
        if (tk == GRID - 1) {
            float tot  = atomicAdd(&g_nll, 0.0f);
            int   totc = atomicAdd(&g_cnt, 0);
            out[0] = tot / fmaxf((float)totc, 1.0f);
            g_nll = 0.0f; g_cnt = 0; g_ticket = 0u;  // reset for next graph replay
        }
    }
}

extern "C" void kernel_launch(void* const* d_in, const int* in_sizes, int n_in,
                              void* d_out, int out_size)
{
    const float* X = nullptr;
    const float* W = nullptr;
    const float* b = nullptr;
    const int* labels = nullptr;
    for (int i = 0; i < n_in; i++) {
        switch (in_sizes[i]) {
            case 33554432: X = (const float*)d_in[i]; break;       // 64*512*1024
            case 16384:    W = (const float*)d_in[i]; break;       // 1024*16
            case KOUT:     b = (const float*)d_in[i]; break;       // 16
            case NOUT:     labels = (const int*)d_in[i]; break;    // 64*512*8
            default: break;
        }
    }
    float* out = (float*)d_out;

    static bool attr_set = false;  // idempotent host-side attribute (no device work)
    if (!attr_set) {
        cudaFuncSetAttribute(rpn_fused_kernel,
                             cudaFuncAttributeMaxDynamicSharedMemorySize, SMEM_TOTAL);
        attr_set = true;
    }

    rpn_fused_kernel<<<GRID, NTHR, SMEM_TOTAL>>>(X, W, b, labels, out);
}

// round 3
// speedup vs baseline: 1.4144x; 1.2143x over previous
#include <cuda_runtime.h>
#include <cstdint>

typedef unsigned long long ull;

#define KOUT     16
#define NOUT     262144        // 64*512*8
#define TILE_R   8
#define NTILES   4096          // 32768 rows / 8
#define GRID     152
#define NTHR     512

// ---- shared memory layout (bytes) ----
#define STAGE_BYTES 32768                  // 8 rows * 4096B, swizzled
#define XS_OFF      0
#define RED_OFF     (2*STAGE_BYTES)        // 65536
#define RED_ULLS    (16*8*16)              // warp x row x k partials
#define LOG_OFF     (RED_OFF + RED_ULLS*8) // 81920
#define BIAS_OFF    (LOG_OFF + 8*16*4)     // 82432
#define PART_OFF    (BIAS_OFF + 64)        // 82496
#define SMEM_TOTAL  (PART_OFF + 128)       // 82624

__device__ float        g_nll;
__device__ int          g_cnt;
__device__ unsigned int g_ticket;

__device__ __forceinline__ ull fma2(ull a, ull b, ull c) {
    ull d;
    asm("fma.rn.f32x2 %0, %1, %2, %3;" : "=l"(d) : "l"(a), "l"(b), "l"(c));
    return d;
}
__device__ __forceinline__ ull add2(ull a, ull b) {
    ull d;
    asm("add.rn.f32x2 %0, %1, %2;" : "=l"(d) : "l"(a), "l"(b));
    return d;
}
__device__ __forceinline__ float lo32(ull v) { return __uint_as_float((unsigned)(v & 0xffffffffu)); }
__device__ __forceinline__ float hi32(ull v) { return __uint_as_float((unsigned)(v >> 32)); }
__device__ __forceinline__ ull pack2(float lo, float hi) {
    return ((ull)__float_as_uint(hi) << 32) | (ull)__float_as_uint(lo);
}

__device__ __forceinline__ void cp16(uint32_t s, const void* g) {
    asm volatile("cp.async.cg.shared.global [%0], [%1], 16;" :: "r"(s), "l"(g) : "memory");
}
#define CP_COMMIT() asm volatile("cp.async.commit_group;" ::: "memory")
#define CP_WAIT1()  asm volatile("cp.async.wait_group 1;" ::: "memory")

// 16B-chunk index swizzle within a 4KB row (classic 128B XOR swizzle)
__device__ __forceinline__ uint32_t swz(uint32_t u) { return u ^ ((u >> 3) & 7u); }

__device__ __forceinline__ void issue_tile_load(const float* __restrict__ X,
                                                uint32_t smem_base, int tile,
                                                int stg, int tid) {
    const char* g = (const char*)X + (size_t)tile * STAGE_BYTES;
    uint32_t sb = smem_base + XS_OFF + (uint32_t)stg * STAGE_BYTES;
    #pragma unroll
    for (int i = 0; i < 4; i++) {                 // 512 thr * 4 * 16B = 32KB
        int c   = tid + i * NTHR;                 // 16B chunk 0..2047
        int row = c >> 8;
        uint32_t u = (uint32_t)(c & 255);
        cp16(sb + (uint32_t)row * 4096u + swz(u) * 16u, g + (size_t)c * 16);
    }
}

__global__ __launch_bounds__(NTHR, 1)
void rpn_fused_kernel(const float* __restrict__ X,
                      const float* __restrict__ W,
                      const float* __restrict__ bvec,
                      const int*   __restrict__ labels,
                      float* __restrict__ out)
{
    extern __shared__ char smem[];
    ull*   red     = (ull*)(smem + RED_OFF);
    float* logit_s = (float*)(smem + LOG_OFF);
    float* bias_s  = (float*)(smem + BIAS_OFF);
    float* pn      = (float*)(smem + PART_OFF);
    int*   pc      = (int*)(smem + PART_OFF + 64);

    const int tid  = threadIdx.x;
    const int w    = tid >> 5;          // warp 0..15
    const int lane = tid & 31;
    const int kh   = lane & 7;          // k-group: k = kh*2 + {0,1}
    const int j    = lane >> 3;         // pair-group within warp (0..3)
    const int pg   = w * 4 + j;         // global pair-group 0..63 (8 pairs = 64B)

    const uint32_t smem_base = (uint32_t)__cvta_generic_to_shared(smem);

    // Prologue: first tile load in flight before anything else
    int t0 = blockIdx.x;
    if (t0 < NTILES) issue_tile_load(X, smem_base, t0, 0, tid);
    CP_COMMIT();

    // W slice -> registers (once): wreg[pp][kk] = (W[2p][k], W[2p+1][k])
    // p = pg*8+pp (pp 0..7), k = kh*2+kk (kk 0..1)
    ull wreg[8][2];
    #pragma unroll
    for (int pp = 0; pp < 8; pp++) {
        int p = pg * 8 + pp;
        #pragma unroll
        for (int kk = 0; kk < 2; kk++) {
            int k = kh * 2 + kk;
            wreg[pp][kk] = pack2(__ldg(&W[p * 32 + k]), __ldg(&W[p * 32 + 16 + k]));
        }
    }
    if (tid < KOUT) bias_s[tid] = bvec[tid];

    float run_nll = 0.0f;
    int   run_cnt = 0;

    int stg = 0;
    for (int t = blockIdx.x; t < NTILES; t += GRID, stg ^= 1) {
        int tn = t + GRID;
        if (tn < NTILES) issue_tile_load(X, smem_base, tn, stg ^ 1, tid);
        CP_COMMIT();
        CP_WAIT1();
        __syncthreads();

        const char* xb = smem + XS_OFF + stg * STAGE_BYTES;

        ull acc[TILE_R][2];
        #pragma unroll
        for (int r = 0; r < TILE_R; r++) { acc[r][0] = 0ULL; acc[r][1] = 0ULL; }

        #pragma unroll
        for (int it = 0; it < 4; it++) {
            uint32_t off = swz((uint32_t)(pg * 4 + it)) * 16u;
            ulonglong2 xv[TILE_R];
            #pragma unroll
            for (int r = 0; r < TILE_R; r++)
                xv[r] = *(const ulonglong2*)(xb + r * 4096 + off);
            #pragma unroll
            for (int r = 0; r < TILE_R; r++) {
                #pragma unroll
                for (int kk = 0; kk < 2; kk++) {
                    acc[r][kk] = fma2(xv[r].x, wreg[it * 2][kk],     acc[r][kk]);
                    acc[r][kk] = fma2(xv[r].y, wreg[it * 2 + 1][kk], acc[r][kk]);
                }
            }
        }

        // Reduce over the 4 pair-groups within the warp (lane bits 3,4)
        #pragma unroll
        for (int r = 0; r < TILE_R; r++) {
            #pragma unroll
            for (int kk = 0; kk < 2; kk++) {
                ull v = acc[r][kk];
                v = add2(v, __shfl_xor_sync(0xffffffffu, v, 8));
                v = add2(v, __shfl_xor_sync(0xffffffffu, v, 16));
                acc[r][kk] = v;
            }
        }
        if (j == 0) {   // lanes 0..7 hold warp partials for k = kh*2, kh*2+1
            #pragma unroll
            for (int r = 0; r < TILE_R; r++) {
                ulonglong2 v; v.x = acc[r][0]; v.y = acc[r][1];
                *(ulonglong2*)&red[w * 128 + r * 16 + kh * 2] = v;
            }
        }
        __syncthreads();

        // Cross-warp: 128 threads = (row, k); sum 16 warp partials
        if (tid < 128) {
            int row = tid >> 4, k = tid & 15;
            ull s = red[row * 16 + k];
            #pragma unroll
            for (int ww = 1; ww < 16; ww++) s = add2(s, red[ww * 128 + row * 16 + k]);
            logit_s[row * 16 + k] = lo32(s) + hi32(s) + bias_s[k];
        }
        __syncthreads();

        // Epilogue: 64 threads = (row, anchor)
        if (tid < 64) {
            int row = tid >> 3, a = tid & 7;
            float l0 = logit_s[row * 16 + 2 * a];
            float l1 = logit_s[row * 16 + 2 * a + 1];
            int gidx = t * 64 + tid;
            int lb = __ldg(&labels[gidx]);
            bool valid = (lb != -1);
            int  pred  = (l1 > l0) ? 1 : 0;
            float chosen = (lb == 1) ? l1 : l0;
            float other  = (lb == 1) ? l0 : l1;
            float d = other - chosen;
            float nll = (d > 0.0f) ? (d + log1pf(expf(-d))) : log1pf(expf(d));
            if (valid) { run_nll += nll; run_cnt++; }
            out[1 + gidx]        = (float)pred;
            out[1 + NOUT + gidx] = (pred == 1 && valid) ? 1.0f : 0.0f;
        }
        __syncthreads();   // all reads of stage stg done before it is refilled
    }

    // ---- loss: warp -> CTA -> chip (last-CTA ticket) ----
    #pragma unroll
    for (int off = 16; off > 0; off >>= 1) {
        run_nll += __shfl_down_sync(0xffffffffu, run_nll, off);
        run_cnt += __shfl_down_sync(0xffffffffu, run_cnt, off);
    }
    if (lane == 0) { pn[w] = run_nll; pc[w] = run_cnt; }
    __syncthreads();
    if (tid == 0) {
        float s = 0.0f; int c = 0;
        #pragma unroll
        for (int ww = 0; ww < 16; ww++) { s += pn[ww]; c += pc[ww]; }
        atomicAdd(&g_nll, s);
        atomicAdd(&g_cnt, c);
        __threadfence();
        unsigned tk = atomicAdd(&g_ticket, 1u);
        if (tk == GRID - 1) {
            float tot  = atomicAdd(&g_nll, 0.0f);
            int   totc = atomicAdd(&g_cnt, 0);
            out[0] = tot / fmaxf((float)totc, 1.0f);
            g_nll = 0.0f; g_cnt = 0; g_ticket = 0u;   // reset for graph replay
        }
    }
}

extern "C" void kernel_launch(void* const* d_in, const int* in_sizes, int n_in,
                              void* d_out, int out_size)
{
    const float* X = nullptr;
    const float* W = nullptr;
    const float* b = nullptr;
    const int* labels = nullptr;
    for (int i = 0; i < n_in; i++) {
        switch (in_sizes[i]) {
            case 33554432: X = (const float*)d_in[i]; break;       // 64*512*1024
            case 16384:    W = (const float*)d_in[i]; break;       // 1024*16
            case KOUT:     b = (const float*)d_in[i]; break;       // 16
            case NOUT:     labels = (const int*)d_in[i]; break;    // 64*512*8
            default: break;
        }
    }
    float* out = (float*)d_out;

    static bool attr_set = false;  // idempotent host-side attribute (no device work)
    if (!attr_set) {
        cudaFuncSetAttribute(rpn_fused_kernel,
                             cudaFuncAttributeMaxDynamicSharedMemorySize, SMEM_TOTAL);
        attr_set = true;
    }

    rpn_fused_kernel<<<GRID, NTHR, SMEM_TOTAL>>>(X, W, b, labels, out);
}